// round 1
// baseline (speedup 1.0000x reference)
#include <cuda_runtime.h>
#include <cstdint>
#include <cstddef>

#define FDIM 128
#define NMAX 100000
#define NCLS 40

// Scratch (static device globals — no runtime allocation).
static __device__ float g_agg[(size_t)NMAX * FDIM];
static __device__ float g_x1[(size_t)NMAX * FDIM];
static __device__ float g_x2[(size_t)NMAX * FDIM];

// ---------------------------------------------------------------------------
// Zero-fill
// ---------------------------------------------------------------------------
__global__ void zero_kernel(float4* __restrict__ p, int n4) {
    int i = blockIdx.x * blockDim.x + threadIdx.x;
    if (i < n4) p[i] = make_float4(0.f, 0.f, 0.f, 0.f);
}

// ---------------------------------------------------------------------------
// Scatter-add: agg[dst[e]] += x[src[e]]  (one warp per edge, v4 reductions)
// ---------------------------------------------------------------------------
__global__ void scatter_kernel(const float* __restrict__ x,
                               const int* __restrict__ src,
                               const int* __restrict__ dst,
                               float* __restrict__ agg, int E) {
    int gw   = (blockIdx.x * blockDim.x + threadIdx.x) >> 5;
    int lane = threadIdx.x & 31;
    int nw   = (gridDim.x * blockDim.x) >> 5;
    for (int e = gw; e < E; e += nw) {
        int s = __ldg(src + e);
        int d = __ldg(dst + e);
        float4 v = *(const float4*)(x + (size_t)s * FDIM + lane * 4);
        float* a = agg + (size_t)d * FDIM + lane * 4;
        asm volatile("red.global.add.v4.f32 [%0], {%1,%2,%3,%4};"
                     :: "l"(a), "f"(v.x), "f"(v.y), "f"(v.z), "f"(v.w)
                     : "memory");
    }
}

// ---------------------------------------------------------------------------
// Fused GraphConv GEMM: C = relu(A1@B1 + A2@B2 + bias)
//   A1,A2: [M,128]  B1,B2: [128,128]  bias: [128]  C: [M,128]
// 128x128 block tile, BK=16, 256 threads, 8x8 microtile, double-buffered smem.
// ---------------------------------------------------------------------------
__global__ __launch_bounds__(256, 2)
void gemm_relu(const float* __restrict__ A1, const float* __restrict__ B1,
               const float* __restrict__ A2, const float* __restrict__ B2,
               const float* __restrict__ bias, float* __restrict__ C, int M) {
    __shared__ float As[2][16][132];   // [k][m], padded
    __shared__ float Bs[2][16][128];   // [k][n]

    const int tid = threadIdx.x;
    const int m0  = blockIdx.x * 128;
    const int tm  = (tid >> 4) << 3;   // output row offset (0..120)
    const int tn  = (tid & 15) << 3;   // output col offset (0..120)

    // A-load mapping: 512 float4 per tile, 2 per thread
    const int arow  = tid >> 2;            // 0..63
    const int aquad = tid & 3;             // 0..3 (covers k quads)
    const int arow2 = arow + 64;
    // B-load mapping: 512 float4 per tile, 2 per thread
    const int bk = tid >> 5;               // 0..7
    const int bn = (tid & 31) << 2;        // 0..124

    float acc[8][8];
#pragma unroll
    for (int i = 0; i < 8; i++)
#pragma unroll
        for (int j = 0; j < 8; j++) acc[i][j] = 0.f;

#define LOAD_TILE(T, BUF) do {                                                  \
    const float* Ap = ((T) < 8) ? A1 : A2;                                      \
    const float* Bp = ((T) < 8) ? B1 : B2;                                      \
    const int kt = ((T) & 7) * 16;                                              \
    float4 fa0 = make_float4(0.f,0.f,0.f,0.f);                                  \
    float4 fa1 = make_float4(0.f,0.f,0.f,0.f);                                  \
    if (m0 + arow  < M) fa0 = *(const float4*)(Ap + (size_t)(m0+arow )*FDIM + kt + aquad*4); \
    if (m0 + arow2 < M) fa1 = *(const float4*)(Ap + (size_t)(m0+arow2)*FDIM + kt + aquad*4); \
    float4 fb0 = *(const float4*)(Bp + (size_t)(kt + bk    )*FDIM + bn);        \
    float4 fb1 = *(const float4*)(Bp + (size_t)(kt + bk + 8)*FDIM + bn);        \
    As[BUF][aquad*4+0][arow ] = fa0.x; As[BUF][aquad*4+1][arow ] = fa0.y;       \
    As[BUF][aquad*4+2][arow ] = fa0.z; As[BUF][aquad*4+3][arow ] = fa0.w;       \
    As[BUF][aquad*4+0][arow2] = fa1.x; As[BUF][aquad*4+1][arow2] = fa1.y;       \
    As[BUF][aquad*4+2][arow2] = fa1.z; As[BUF][aquad*4+3][arow2] = fa1.w;       \
    *(float4*)&Bs[BUF][bk    ][bn] = fb0;                                       \
    *(float4*)&Bs[BUF][bk + 8][bn] = fb1;                                       \
} while (0)

    LOAD_TILE(0, 0);
    __syncthreads();

    for (int t = 0; t < 16; t++) {
        const int buf = t & 1;
        if (t < 15) LOAD_TILE(t + 1, buf ^ 1);
#pragma unroll
        for (int k = 0; k < 16; k++) {
            float4 a0 = *(const float4*)&As[buf][k][tm];
            float4 a1 = *(const float4*)&As[buf][k][tm + 4];
            float4 b0 = *(const float4*)&Bs[buf][k][tn];
            float4 b1 = *(const float4*)&Bs[buf][k][tn + 4];
            float av[8] = {a0.x, a0.y, a0.z, a0.w, a1.x, a1.y, a1.z, a1.w};
            float bv[8] = {b0.x, b0.y, b0.z, b0.w, b1.x, b1.y, b1.z, b1.w};
#pragma unroll
            for (int i = 0; i < 8; i++)
#pragma unroll
                for (int j = 0; j < 8; j++) acc[i][j] += av[i] * bv[j];
        }
        __syncthreads();
    }
#undef LOAD_TILE

    float bb[8];
#pragma unroll
    for (int j = 0; j < 8; j++) bb[j] = __ldg(bias + tn + j);

#pragma unroll
    for (int i = 0; i < 8; i++) {
        int r = m0 + tm + i;
        if (r < M) {
            float4 o0, o1;
            o0.x = fmaxf(acc[i][0] + bb[0], 0.f);
            o0.y = fmaxf(acc[i][1] + bb[1], 0.f);
            o0.z = fmaxf(acc[i][2] + bb[2], 0.f);
            o0.w = fmaxf(acc[i][3] + bb[3], 0.f);
            o1.x = fmaxf(acc[i][4] + bb[4], 0.f);
            o1.y = fmaxf(acc[i][5] + bb[5], 0.f);
            o1.z = fmaxf(acc[i][6] + bb[6], 0.f);
            o1.w = fmaxf(acc[i][7] + bb[7], 0.f);
            *(float4*)(C + (size_t)r * FDIM + tn)     = o0;
            *(float4*)(C + (size_t)r * FDIM + tn + 4) = o1;
        }
    }
}

// ---------------------------------------------------------------------------
// Head: out = log_softmax(concat(x1,x2) @ W_lin + b_lin)
// Warp per node. Lane = 4*k8 + c4: k strided by 8, classes split 4x10.
// ---------------------------------------------------------------------------
__global__ __launch_bounds__(256)
void head_kernel(const float* __restrict__ x1, const float* __restrict__ x2,
                 const float* __restrict__ Wl, const float* __restrict__ bl,
                 float* __restrict__ out, int N) {
    __shared__ float Ws[256 * NCLS + NCLS];
    for (int i = threadIdx.x; i < 256 * NCLS; i += blockDim.x) Ws[i] = Wl[i];
    if (threadIdx.x < NCLS) Ws[256 * NCLS + threadIdx.x] = bl[threadIdx.x];
    __syncthreads();

    const int lane = threadIdx.x & 31;
    const int warp = threadIdx.x >> 5;
    const int c4   = lane & 3;    // class group: classes c4*10 .. c4*10+9
    const int k8   = lane >> 2;   // k offset 0..7, stride 8

    for (int node = blockIdx.x * 8 + warp; node < N; node += gridDim.x * 8) {
        float acc[10];
#pragma unroll
        for (int c = 0; c < 10; c++) acc[c] = 0.f;
        const float* h1 = x1 + (size_t)node * FDIM;
        const float* h2 = x2 + (size_t)node * FDIM;
#pragma unroll
        for (int kk = 0; kk < 16; kk++) {
            int k = k8 + kk * 8;
            float v1 = __ldg(h1 + k);
            float v2 = __ldg(h2 + k);
            const float* w1 = Ws + k * NCLS + c4 * 10;
            const float* w2 = Ws + (128 + k) * NCLS + c4 * 10;
#pragma unroll
            for (int c = 0; c < 10; c++) acc[c] += v1 * w1[c] + v2 * w2[c];
        }
        // reduce across k8 (lanes differing in bits 2..4)
#pragma unroll
        for (int m = 4; m < 32; m <<= 1)
#pragma unroll
            for (int c = 0; c < 10; c++)
                acc[c] += __shfl_xor_sync(0xffffffffu, acc[c], m);
#pragma unroll
        for (int c = 0; c < 10; c++) acc[c] += Ws[256 * NCLS + c4 * 10 + c];

        float mx = acc[0];
#pragma unroll
        for (int c = 1; c < 10; c++) mx = fmaxf(mx, acc[c]);
        mx = fmaxf(mx, __shfl_xor_sync(0xffffffffu, mx, 1));
        mx = fmaxf(mx, __shfl_xor_sync(0xffffffffu, mx, 2));
        float se = 0.f;
#pragma unroll
        for (int c = 0; c < 10; c++) se += expf(acc[c] - mx);
        se += __shfl_xor_sync(0xffffffffu, se, 1);
        se += __shfl_xor_sync(0xffffffffu, se, 2);
        float lse = logf(se);
        if (k8 == 0) {
            float* o = out + (size_t)node * NCLS + c4 * 10;
#pragma unroll
            for (int c = 0; c < 10; c++) o[c] = acc[c] - mx - lse;
        }
    }
}

// ---------------------------------------------------------------------------
// kernel_launch
// ---------------------------------------------------------------------------
extern "C" void kernel_launch(void* const* d_in, const int* in_sizes, int n_in,
                              void* d_out, int out_size) {
    const float* x    = (const float*)d_in[0];
    const int*   ei   = (const int*)d_in[1];
    const float* Wr1  = (const float*)d_in[2];
    const float* b1   = (const float*)d_in[3];
    const float* Wt1  = (const float*)d_in[4];
    const float* Wr2  = (const float*)d_in[5];
    const float* b2   = (const float*)d_in[6];
    const float* Wt2  = (const float*)d_in[7];
    const float* Wl   = (const float*)d_in[8];
    const float* bl   = (const float*)d_in[9];
    float*       out  = (float*)d_out;

    const int N = in_sizes[0] / FDIM;
    const int E = in_sizes[1] / 2;
    const int* src = ei;
    const int* dst = ei + E;

    float *agg, *x1, *x2;
    cudaGetSymbolAddress((void**)&agg, g_agg);
    cudaGetSymbolAddress((void**)&x1,  g_x1);
    cudaGetSymbolAddress((void**)&x2,  g_x2);

    const int n4       = N * FDIM / 4;
    const int zeroBlk  = (n4 + 255) / 256;
    const int scatBlk  = 8192;
    const int gemmBlk  = (N + 127) / 128;
    const int headBlk  = 1024;

    // Layer 1
    zero_kernel<<<zeroBlk, 256>>>((float4*)agg, n4);
    scatter_kernel<<<scatBlk, 256>>>(x, src, dst, agg, E);
    gemm_relu<<<gemmBlk, 256>>>(agg, Wr1, x, Wt1, b1, x1, N);

    // Layer 2
    zero_kernel<<<zeroBlk, 256>>>((float4*)agg, n4);
    scatter_kernel<<<scatBlk, 256>>>(x1, src, dst, agg, E);
    gemm_relu<<<gemmBlk, 256>>>(agg, Wr2, x1, Wt2, b2, x2, N);

    // Head
    head_kernel<<<headBlk, 256>>>(x1, x2, Wl, bl, out, N);
}

// round 6
// speedup vs baseline: 1.9426x; 1.9426x over previous
#include <cuda_runtime.h>
#include <cstdint>
#include <cstddef>

#define FDIM 128
#define NMAX 100000
#define NCLS 40

static __device__ float g_agg[(size_t)NMAX * FDIM];
static __device__ float g_x1[(size_t)NMAX * FDIM];
static __device__ float g_x2[(size_t)NMAX * FDIM];

// ---------------------------------------------------------------------------
// Zero-fill
// ---------------------------------------------------------------------------
__global__ void zero_kernel(float4* __restrict__ p, int n4) {
    int i = blockIdx.x * blockDim.x + threadIdx.x;
    if (i < n4) p[i] = make_float4(0.f, 0.f, 0.f, 0.f);
}

// ---------------------------------------------------------------------------
// Scatter-add: agg[dst[e]] += x[src[e]]  (one warp per edge, v4 reductions)
// ---------------------------------------------------------------------------
__global__ void scatter_kernel(const float* __restrict__ x,
                               const int* __restrict__ src,
                               const int* __restrict__ dst,
                               float* __restrict__ agg, int E) {
    int gw   = (blockIdx.x * blockDim.x + threadIdx.x) >> 5;
    int lane = threadIdx.x & 31;
    int nw   = (gridDim.x * blockDim.x) >> 5;
    for (int e = gw; e < E; e += nw) {
        int s = __ldg(src + e);
        int d = __ldg(dst + e);
        float4 v = *(const float4*)(x + (size_t)s * FDIM + lane * 4);
        float* a = agg + (size_t)d * FDIM + lane * 4;
        asm volatile("red.global.add.v4.f32 [%0], {%1,%2,%3,%4};"
                     :: "l"(a), "f"(v.x), "f"(v.y), "f"(v.z), "f"(v.w)
                     : "memory");
    }
}

// ---------------------------------------------------------------------------
// Tensor-core TF32 fused GraphConv GEMM:
//   C = relu(A1@B1 + A2@B2 + bias),  A:[M,128] B:[128,128] C:[M,128]
// CTA tile 128x128, BK=16 (16 chunks over logical K=256), 256 threads,
// 8 warps of 64x32 tiles, mma.sync.m16n8k8.tf32, double-buffered smem.
// As: k-major stride 129 (conflict-free STS); Bs: k-major stride 132.
// ---------------------------------------------------------------------------
#define AS_STRIDE 129
#define BS_STRIDE 132

__device__ __forceinline__ uint32_t f2tf32(float f) {
    uint32_t r;
    asm("cvt.rna.tf32.f32 %0, %1;" : "=r"(r) : "f"(f));
    return r;
}

__global__ __launch_bounds__(256, 2)
void gemm_tc(const float* __restrict__ A1, const float* __restrict__ B1,
             const float* __restrict__ A2, const float* __restrict__ B2,
             const float* __restrict__ bias, float* __restrict__ C, int M) {
    __shared__ uint32_t As[2][16 * AS_STRIDE];   // [k][m]
    __shared__ uint32_t Bs[2][16 * BS_STRIDE];   // [k][n]

    const int tid  = threadIdx.x;
    const int lane = tid & 31;
    const int g    = lane >> 2;       // groupID
    const int t    = lane & 3;        // thread in group
    const int warp = tid >> 5;
    const int wm   = (warp >> 2) * 64;    // 0 / 64
    const int wn   = (warp & 3) * 32;     // 0 / 32 / 64 / 96
    const int m0   = blockIdx.x * 128;

    // Global-load mapping
    const int arow0 = tid >> 1;               // A: idx=tid*? -> use idx=tid+i*256
    (void)arow0;

    float acc[4][4][4];
#pragma unroll
    for (int mi = 0; mi < 4; mi++)
#pragma unroll
        for (int ni = 0; ni < 4; ni++)
#pragma unroll
            for (int j = 0; j < 4; j++) acc[mi][ni][j] = 0.f;

    float4 ra[2], rb[2];

#define LDG_CHUNK(T) do {                                                       \
    const float* Ap = ((T) < 8) ? A1 : A2;                                      \
    const float* Bp = ((T) < 8) ? B1 : B2;                                      \
    const int kt = ((T) & 7) * 16;                                              \
    _Pragma("unroll")                                                           \
    for (int i = 0; i < 2; i++) {                                               \
        int idx  = tid + i * 256;                                               \
        int row  = idx >> 2;            /* 0..127 */                            \
        int colq = idx & 3;             /* 0..3   */                            \
        ra[i] = make_float4(0.f, 0.f, 0.f, 0.f);                                \
        if (m0 + row < M)                                                       \
            ra[i] = *(const float4*)(Ap + (size_t)(m0 + row) * FDIM + kt + colq * 4); \
        int k   = idx >> 5;             /* 0..15  */                            \
        int n4  = idx & 31;             /* 0..31  */                            \
        rb[i] = *(const float4*)(Bp + (size_t)(kt + k) * FDIM + n4 * 4);        \
    }                                                                           \
} while (0)

#define STS_CHUNK(BUF) do {                                                     \
    _Pragma("unroll")                                                           \
    for (int i = 0; i < 2; i++) {                                               \
        int idx  = tid + i * 256;                                               \
        int row  = idx >> 2;                                                    \
        int colq = idx & 3;                                                     \
        As[BUF][(colq * 4 + 0) * AS_STRIDE + row] = f2tf32(ra[i].x);            \
        As[BUF][(colq * 4 + 1) * AS_STRIDE + row] = f2tf32(ra[i].y);            \
        As[BUF][(colq * 4 + 2) * AS_STRIDE + row] = f2tf32(ra[i].z);            \
        As[BUF][(colq * 4 + 3) * AS_STRIDE + row] = f2tf32(ra[i].w);            \
        int k  = idx >> 5;                                                      \
        int n4 = idx & 31;                                                      \
        uint32_t* bp = &Bs[BUF][k * BS_STRIDE + n4 * 4];                        \
        bp[0] = f2tf32(rb[i].x); bp[1] = f2tf32(rb[i].y);                       \
        bp[2] = f2tf32(rb[i].z); bp[3] = f2tf32(rb[i].w);                       \
    }                                                                           \
} while (0)

#define COMPUTE(BUF) do {                                                       \
    _Pragma("unroll")                                                           \
    for (int ks = 0; ks < 2; ks++) {                                            \
        uint32_t af[4][4];                                                      \
        uint32_t bf[4][2];                                                      \
        _Pragma("unroll")                                                       \
        for (int mi = 0; mi < 4; mi++) {                                        \
            int mb = wm + mi * 16;                                              \
            af[mi][0] = As[BUF][(ks * 8 + t    ) * AS_STRIDE + mb + g    ];     \
            af[mi][1] = As[BUF][(ks * 8 + t    ) * AS_STRIDE + mb + g + 8];     \
            af[mi][2] = As[BUF][(ks * 8 + t + 4) * AS_STRIDE + mb + g    ];     \
            af[mi][3] = As[BUF][(ks * 8 + t + 4) * AS_STRIDE + mb + g + 8];     \
        }                                                                       \
        _Pragma("unroll")                                                       \
        for (int ni = 0; ni < 4; ni++) {                                        \
            int nb = wn + ni * 8;                                               \
            bf[ni][0] = Bs[BUF][(ks * 8 + t    ) * BS_STRIDE + nb + g];         \
            bf[ni][1] = Bs[BUF][(ks * 8 + t + 4) * BS_STRIDE + nb + g];         \
        }                                                                       \
        _Pragma("unroll")                                                       \
        for (int mi = 0; mi < 4; mi++)                                          \
        _Pragma("unroll")                                                       \
        for (int ni = 0; ni < 4; ni++) {                                        \
            asm volatile(                                                       \
                "mma.sync.aligned.m16n8k8.row.col.f32.tf32.tf32.f32 "           \
                "{%0,%1,%2,%3}, {%4,%5,%6,%7}, {%8,%9}, {%0,%1,%2,%3};"         \
                : "+f"(acc[mi][ni][0]), "+f"(acc[mi][ni][1]),                   \
                  "+f"(acc[mi][ni][2]), "+f"(acc[mi][ni][3])                    \
                : "r"(af[mi][0]), "r"(af[mi][1]), "r"(af[mi][2]), "r"(af[mi][3]), \
                  "r"(bf[ni][0]), "r"(bf[ni][1]));                              \
        }                                                                       \
    }                                                                           \
} while (0)

    LDG_CHUNK(0);
    STS_CHUNK(0);
    __syncthreads();

    for (int tch = 0; tch < 16; tch++) {
        const int buf = tch & 1;
        if (tch < 15) LDG_CHUNK(tch + 1);
        COMPUTE(buf);
        if (tch < 15) {
            STS_CHUNK(buf ^ 1);
            __syncthreads();
        }
    }
#undef LDG_CHUNK
#undef STS_CHUNK
#undef COMPUTE

    // Epilogue: bias + relu + store (float2 per fragment half-row)
    float2 bb[4];
#pragma unroll
    for (int ni = 0; ni < 4; ni++) {
        int col = wn + ni * 8 + t * 2;
        bb[ni].x = __ldg(bias + col);
        bb[ni].y = __ldg(bias + col + 1);
    }
#pragma unroll
    for (int mi = 0; mi < 4; mi++) {
        int row0 = m0 + wm + mi * 16 + g;
        int row1 = row0 + 8;
#pragma unroll
        for (int ni = 0; ni < 4; ni++) {
            int col = wn + ni * 8 + t * 2;
            if (row0 < M) {
                float2 v;
                v.x = fmaxf(acc[mi][ni][0] + bb[ni].x, 0.f);
                v.y = fmaxf(acc[mi][ni][1] + bb[ni].y, 0.f);
                *(float2*)(C + (size_t)row0 * FDIM + col) = v;
            }
            if (row1 < M) {
                float2 v;
                v.x = fmaxf(acc[mi][ni][2] + bb[ni].x, 0.f);
                v.y = fmaxf(acc[mi][ni][3] + bb[ni].y, 0.f);
                *(float2*)(C + (size_t)row1 * FDIM + col) = v;
            }
        }
    }
}

// ---------------------------------------------------------------------------
// Head: out = log_softmax(concat(x1,x2) @ W_lin + b_lin)
// ---------------------------------------------------------------------------
__global__ __launch_bounds__(256)
void head_kernel(const float* __restrict__ x1, const float* __restrict__ x2,
                 const float* __restrict__ Wl, const float* __restrict__ bl,
                 float* __restrict__ out, int N) {
    __shared__ float Ws[256 * NCLS + NCLS];
    for (int i = threadIdx.x; i < 256 * NCLS; i += blockDim.x) Ws[i] = Wl[i];
    if (threadIdx.x < NCLS) Ws[256 * NCLS + threadIdx.x] = bl[threadIdx.x];
    __syncthreads();

    const int lane = threadIdx.x & 31;
    const int warp = threadIdx.x >> 5;
    const int c4   = lane & 3;
    const int k8   = lane >> 2;

    for (int node = blockIdx.x * 8 + warp; node < N; node += gridDim.x * 8) {
        float acc[10];
#pragma unroll
        for (int c = 0; c < 10; c++) acc[c] = 0.f;
        const float* h1 = x1 + (size_t)node * FDIM;
        const float* h2 = x2 + (size_t)node * FDIM;
#pragma unroll
        for (int kk = 0; kk < 16; kk++) {
            int k = k8 + kk * 8;
            float v1 = __ldg(h1 + k);
            float v2 = __ldg(h2 + k);
            const float* w1 = Ws + k * NCLS + c4 * 10;
            const float* w2 = Ws + (128 + k) * NCLS + c4 * 10;
#pragma unroll
            for (int c = 0; c < 10; c++) acc[c] += v1 * w1[c] + v2 * w2[c];
        }
#pragma unroll
        for (int m = 4; m < 32; m <<= 1)
#pragma unroll
            for (int c = 0; c < 10; c++)
                acc[c] += __shfl_xor_sync(0xffffffffu, acc[c], m);
#pragma unroll
        for (int c = 0; c < 10; c++) acc[c] += Ws[256 * NCLS + c4 * 10 + c];

        float mx = acc[0];
#pragma unroll
        for (int c = 1; c < 10; c++) mx = fmaxf(mx, acc[c]);
        mx = fmaxf(mx, __shfl_xor_sync(0xffffffffu, mx, 1));
        mx = fmaxf(mx, __shfl_xor_sync(0xffffffffu, mx, 2));
        float se = 0.f;
#pragma unroll
        for (int c = 0; c < 10; c++) se += expf(acc[c] - mx);
        se += __shfl_xor_sync(0xffffffffu, se, 1);
        se += __shfl_xor_sync(0xffffffffu, se, 2);
        float lse = logf(se);
        if (k8 == 0) {
            float* o = out + (size_t)node * NCLS + c4 * 10;
#pragma unroll
            for (int c = 0; c < 10; c++) o[c] = acc[c] - mx - lse;
        }
    }
}

// ---------------------------------------------------------------------------
// kernel_launch
// ---------------------------------------------------------------------------
extern "C" void kernel_launch(void* const* d_in, const int* in_sizes, int n_in,
                              void* d_out, int out_size) {
    const float* x    = (const float*)d_in[0];
    const int*   ei   = (const int*)d_in[1];
    const float* Wr1  = (const float*)d_in[2];
    const float* b1   = (const float*)d_in[3];
    const float* Wt1  = (const float*)d_in[4];
    const float* Wr2  = (const float*)d_in[5];
    const float* b2   = (const float*)d_in[6];
    const float* Wt2  = (const float*)d_in[7];
    const float* Wl   = (const float*)d_in[8];
    const float* bl   = (const float*)d_in[9];
    float*       out  = (float*)d_out;

    const int N = in_sizes[0] / FDIM;
    const int E = in_sizes[1] / 2;
    const int* src = ei;
    const int* dst = ei + E;

    float *agg, *x1, *x2;
    cudaGetSymbolAddress((void**)&agg, g_agg);
    cudaGetSymbolAddress((void**)&x1,  g_x1);
    cudaGetSymbolAddress((void**)&x2,  g_x2);

    const int n4       = N * FDIM / 4;
    const int zeroBlk  = (n4 + 255) / 256;
    const int scatBlk  = 8192;
    const int gemmBlk  = (N + 127) / 128;
    const int headBlk  = 1024;

    // Layer 1: agg = scatter(x); x1 = relu(agg@Wr1 + x@Wt1 + b1)
    zero_kernel<<<zeroBlk, 256>>>((float4*)agg, n4);
    scatter_kernel<<<scatBlk, 256>>>(x, src, dst, agg, E);
    gemm_tc<<<gemmBlk, 256>>>(agg, Wr1, x, Wt1, b1, x1, N);

    // Layer 2
    zero_kernel<<<zeroBlk, 256>>>((float4*)agg, n4);
    scatter_kernel<<<scatBlk, 256>>>(x1, src, dst, agg, E);
    gemm_tc<<<gemmBlk, 256>>>(agg, Wr2, x1, Wt2, b2, x2, N);

    // Head
    head_kernel<<<headBlk, 256>>>(x1, x2, Wl, bl, out, N);
}

// round 8
// speedup vs baseline: 2.5173x; 1.2959x over previous
#include <cuda_runtime.h>
#include <cstdint>
#include <cstddef>

#define FDIM 128
#define NMAX 100000
#define EMAX 1700000
#define NCLS 40
#define SCAN_BLK 256

static __device__ float g_agg[(size_t)NMAX * FDIM];
static __device__ float g_x1[(size_t)NMAX * FDIM];
static __device__ float g_x2[(size_t)NMAX * FDIM];
static __device__ int   g_deg[NMAX];
static __device__ int   g_rowptr[NMAX];
static __device__ int   g_cursor[NMAX];
static __device__ int   g_csr[EMAX];
static __device__ int   g_bsum[1024];
static __device__ int   g_boff[1024];

// ---------------------------------------------------------------------------
// CSR build
// ---------------------------------------------------------------------------
__global__ void zero_int_kernel(int* __restrict__ p, int n) {
    int i = blockIdx.x * blockDim.x + threadIdx.x;
    if (i < n) p[i] = 0;
}

__global__ void hist_kernel(const int* __restrict__ dst, int* __restrict__ deg, int E) {
    int e = blockIdx.x * blockDim.x + threadIdx.x;
    if (e < E) atomicAdd(deg + __ldg(dst + e), 1);
}

// per-block sums of deg
__global__ void bsum_kernel(const int* __restrict__ deg, int* __restrict__ bsum, int N) {
    __shared__ int s[SCAN_BLK];
    int i = blockIdx.x * SCAN_BLK + threadIdx.x;
    int v = (i < N) ? deg[i] : 0;
    s[threadIdx.x] = v;
    __syncthreads();
    for (int off = SCAN_BLK / 2; off > 0; off >>= 1) {
        if (threadIdx.x < off) s[threadIdx.x] += s[threadIdx.x + off];
        __syncthreads();
    }
    if (threadIdx.x == 0) bsum[blockIdx.x] = s[0];
}

// exclusive scan of up to 1024 block sums (single block)
__global__ void scan_bsum_kernel(const int* __restrict__ bsum, int* __restrict__ boff, int NB) {
    __shared__ int s[1024];
    int t = threadIdx.x;
    int v = (t < NB) ? bsum[t] : 0;
    s[t] = v;
    __syncthreads();
    for (int off = 1; off < 1024; off <<= 1) {
        int x = (t >= off) ? s[t - off] : 0;
        __syncthreads();
        s[t] += x;
        __syncthreads();
    }
    boff[t] = s[t] - v;   // exclusive
}

// per-block exclusive scan + offset -> rowptr, cursor
__global__ void scan_final_kernel(const int* __restrict__ deg, const int* __restrict__ boff,
                                  int* __restrict__ rowptr, int* __restrict__ cursor, int N) {
    __shared__ int s[SCAN_BLK];
    int i = blockIdx.x * SCAN_BLK + threadIdx.x;
    int t = threadIdx.x;
    int v = (i < N) ? deg[i] : 0;
    s[t] = v;
    __syncthreads();
    for (int off = 1; off < SCAN_BLK; off <<= 1) {
        int x = (t >= off) ? s[t - off] : 0;
        __syncthreads();
        s[t] += x;
        __syncthreads();
    }
    if (i < N) {
        int r = boff[blockIdx.x] + s[t] - v;
        rowptr[i] = r;
        cursor[i] = r;
    }
}

__global__ void fill_kernel(const int* __restrict__ src, const int* __restrict__ dst,
                            int* __restrict__ cursor, int* __restrict__ csr, int E) {
    int e = blockIdx.x * blockDim.x + threadIdx.x;
    if (e < E) {
        int pos = atomicAdd(cursor + __ldg(dst + e), 1);
        csr[pos] = __ldg(src + e);
    }
}

// ---------------------------------------------------------------------------
// Gather-aggregate: agg[i] = sum_{j in N(i)} x[j].  One warp per node.
// ---------------------------------------------------------------------------
__global__ __launch_bounds__(256)
void aggregate_kernel(const float* __restrict__ x,
                      const int* __restrict__ rowptr,
                      const int* __restrict__ deg,
                      const int* __restrict__ csr,
                      float* __restrict__ agg, int N) {
    int node = blockIdx.x * 8 + (threadIdx.x >> 5);
    if (node >= N) return;
    int lane = threadIdx.x & 31;
    int start = __ldg(rowptr + node);
    int end   = start + __ldg(deg + node);

    float4 acc = make_float4(0.f, 0.f, 0.f, 0.f);
    int p = start;
    int j = (p < end) ? __ldg(csr + p) : 0;
    while (p < end) {
        int jn = (p + 1 < end) ? __ldg(csr + p + 1) : 0;
        float4 v = *(const float4*)(x + (size_t)j * FDIM + lane * 4);
        acc.x += v.x; acc.y += v.y; acc.z += v.z; acc.w += v.w;
        j = jn; ++p;
    }
    *(float4*)(agg + (size_t)node * FDIM + lane * 4) = acc;
}

// ---------------------------------------------------------------------------
// Tensor-core TF32 fused GraphConv GEMM (unchanged from R5)
// ---------------------------------------------------------------------------
#define AS_STRIDE 129
#define BS_STRIDE 132

__device__ __forceinline__ uint32_t f2tf32(float f) {
    uint32_t r;
    asm("cvt.rna.tf32.f32 %0, %1;" : "=r"(r) : "f"(f));
    return r;
}

__global__ __launch_bounds__(256, 2)
void gemm_tc(const float* __restrict__ A1, const float* __restrict__ B1,
             const float* __restrict__ A2, const float* __restrict__ B2,
             const float* __restrict__ bias, float* __restrict__ C, int M) {
    __shared__ uint32_t As[2][16 * AS_STRIDE];   // [k][m]
    __shared__ uint32_t Bs[2][16 * BS_STRIDE];   // [k][n]

    const int tid  = threadIdx.x;
    const int lane = tid & 31;
    const int g    = lane >> 2;
    const int t    = lane & 3;
    const int warp = tid >> 5;
    const int wm   = (warp >> 2) * 64;
    const int wn   = (warp & 3) * 32;
    const int m0   = blockIdx.x * 128;

    float acc[4][4][4];
#pragma unroll
    for (int mi = 0; mi < 4; mi++)
#pragma unroll
        for (int ni = 0; ni < 4; ni++)
#pragma unroll
            for (int j = 0; j < 4; j++) acc[mi][ni][j] = 0.f;

    float4 ra[2], rb[2];

#define LDG_CHUNK(T) do {                                                       \
    const float* Ap = ((T) < 8) ? A1 : A2;                                      \
    const float* Bp = ((T) < 8) ? B1 : B2;                                      \
    const int kt = ((T) & 7) * 16;                                              \
    _Pragma("unroll")                                                           \
    for (int i = 0; i < 2; i++) {                                               \
        int idx  = tid + i * 256;                                               \
        int row  = idx >> 2;                                                    \
        int colq = idx & 3;                                                     \
        ra[i] = make_float4(0.f, 0.f, 0.f, 0.f);                                \
        if (m0 + row < M)                                                       \
            ra[i] = *(const float4*)(Ap + (size_t)(m0 + row) * FDIM + kt + colq * 4); \
        int k   = idx >> 5;                                                     \
        int n4  = idx & 31;                                                     \
        rb[i] = *(const float4*)(Bp + (size_t)(kt + k) * FDIM + n4 * 4);        \
    }                                                                           \
} while (0)

#define STS_CHUNK(BUF) do {                                                     \
    _Pragma("unroll")                                                           \
    for (int i = 0; i < 2; i++) {                                               \
        int idx  = tid + i * 256;                                               \
        int row  = idx >> 2;                                                    \
        int colq = idx & 3;                                                     \
        As[BUF][(colq * 4 + 0) * AS_STRIDE + row] = f2tf32(ra[i].x);            \
        As[BUF][(colq * 4 + 1) * AS_STRIDE + row] = f2tf32(ra[i].y);            \
        As[BUF][(colq * 4 + 2) * AS_STRIDE + row] = f2tf32(ra[i].z);            \
        As[BUF][(colq * 4 + 3) * AS_STRIDE + row] = f2tf32(ra[i].w);            \
        int k  = idx >> 5;                                                      \
        int n4 = idx & 31;                                                      \
        uint32_t* bp = &Bs[BUF][k * BS_STRIDE + n4 * 4];                        \
        bp[0] = f2tf32(rb[i].x); bp[1] = f2tf32(rb[i].y);                       \
        bp[2] = f2tf32(rb[i].z); bp[3] = f2tf32(rb[i].w);                       \
    }                                                                           \
} while (0)

#define COMPUTE(BUF) do {                                                       \
    _Pragma("unroll")                                                           \
    for (int ks = 0; ks < 2; ks++) {                                            \
        uint32_t af[4][4];                                                      \
        uint32_t bf[4][2];                                                      \
        _Pragma("unroll")                                                       \
        for (int mi = 0; mi < 4; mi++) {                                        \
            int mb = wm + mi * 16;                                              \
            af[mi][0] = As[BUF][(ks * 8 + t    ) * AS_STRIDE + mb + g    ];     \
            af[mi][1] = As[BUF][(ks * 8 + t    ) * AS_STRIDE + mb + g + 8];     \
            af[mi][2] = As[BUF][(ks * 8 + t + 4) * AS_STRIDE + mb + g    ];     \
            af[mi][3] = As[BUF][(ks * 8 + t + 4) * AS_STRIDE + mb + g + 8];     \
        }                                                                       \
        _Pragma("unroll")                                                       \
        for (int ni = 0; ni < 4; ni++) {                                        \
            int nb = wn + ni * 8;                                               \
            bf[ni][0] = Bs[BUF][(ks * 8 + t    ) * BS_STRIDE + nb + g];         \
            bf[ni][1] = Bs[BUF][(ks * 8 + t + 4) * BS_STRIDE + nb + g];         \
        }                                                                       \
        _Pragma("unroll")                                                       \
        for (int mi = 0; mi < 4; mi++)                                          \
        _Pragma("unroll")                                                       \
        for (int ni = 0; ni < 4; ni++) {                                        \
            asm volatile(                                                       \
                "mma.sync.aligned.m16n8k8.row.col.f32.tf32.tf32.f32 "           \
                "{%0,%1,%2,%3}, {%4,%5,%6,%7}, {%8,%9}, {%0,%1,%2,%3};"         \
                : "+f"(acc[mi][ni][0]), "+f"(acc[mi][ni][1]),                   \
                  "+f"(acc[mi][ni][2]), "+f"(acc[mi][ni][3])                    \
                : "r"(af[mi][0]), "r"(af[mi][1]), "r"(af[mi][2]), "r"(af[mi][3]), \
                  "r"(bf[ni][0]), "r"(bf[ni][1]));                              \
        }                                                                       \
    }                                                                           \
} while (0)

    LDG_CHUNK(0);
    STS_CHUNK(0);
    __syncthreads();

    for (int tch = 0; tch < 16; tch++) {
        const int buf = tch & 1;
        if (tch < 15) LDG_CHUNK(tch + 1);
        COMPUTE(buf);
        if (tch < 15) {
            STS_CHUNK(buf ^ 1);
            __syncthreads();
        }
    }
#undef LDG_CHUNK
#undef STS_CHUNK
#undef COMPUTE

    float2 bb[4];
#pragma unroll
    for (int ni = 0; ni < 4; ni++) {
        int col = wn + ni * 8 + t * 2;
        bb[ni].x = __ldg(bias + col);
        bb[ni].y = __ldg(bias + col + 1);
    }
#pragma unroll
    for (int mi = 0; mi < 4; mi++) {
        int row0 = m0 + wm + mi * 16 + g;
        int row1 = row0 + 8;
#pragma unroll
        for (int ni = 0; ni < 4; ni++) {
            int col = wn + ni * 8 + t * 2;
            if (row0 < M) {
                float2 v;
                v.x = fmaxf(acc[mi][ni][0] + bb[ni].x, 0.f);
                v.y = fmaxf(acc[mi][ni][1] + bb[ni].y, 0.f);
                *(float2*)(C + (size_t)row0 * FDIM + col) = v;
            }
            if (row1 < M) {
                float2 v;
                v.x = fmaxf(acc[mi][ni][2] + bb[ni].x, 0.f);
                v.y = fmaxf(acc[mi][ni][3] + bb[ni].y, 0.f);
                *(float2*)(C + (size_t)row1 * FDIM + col) = v;
            }
        }
    }
}

// ---------------------------------------------------------------------------
// Head: out = log_softmax(concat(x1,x2) @ W_lin + b_lin)
// ---------------------------------------------------------------------------
__global__ __launch_bounds__(256)
void head_kernel(const float* __restrict__ x1, const float* __restrict__ x2,
                 const float* __restrict__ Wl, const float* __restrict__ bl,
                 float* __restrict__ out, int N) {
    __shared__ float Ws[256 * NCLS + NCLS];
    for (int i = threadIdx.x; i < 256 * NCLS; i += blockDim.x) Ws[i] = Wl[i];
    if (threadIdx.x < NCLS) Ws[256 * NCLS + threadIdx.x] = bl[threadIdx.x];
    __syncthreads();

    const int lane = threadIdx.x & 31;
    const int warp = threadIdx.x >> 5;
    const int c4   = lane & 3;
    const int k8   = lane >> 2;

    for (int node = blockIdx.x * 8 + warp; node < N; node += gridDim.x * 8) {
        float acc[10];
#pragma unroll
        for (int c = 0; c < 10; c++) acc[c] = 0.f;
        const float* h1 = x1 + (size_t)node * FDIM;
        const float* h2 = x2 + (size_t)node * FDIM;
#pragma unroll
        for (int kk = 0; kk < 16; kk++) {
            int k = k8 + kk * 8;
            float v1 = __ldg(h1 + k);
            float v2 = __ldg(h2 + k);
            const float* w1 = Ws + k * NCLS + c4 * 10;
            const float* w2 = Ws + (128 + k) * NCLS + c4 * 10;
#pragma unroll
            for (int c = 0; c < 10; c++) acc[c] += v1 * w1[c] + v2 * w2[c];
        }
#pragma unroll
        for (int m = 4; m < 32; m <<= 1)
#pragma unroll
            for (int c = 0; c < 10; c++)
                acc[c] += __shfl_xor_sync(0xffffffffu, acc[c], m);
#pragma unroll
        for (int c = 0; c < 10; c++) acc[c] += Ws[256 * NCLS + c4 * 10 + c];

        float mx = acc[0];
#pragma unroll
        for (int c = 1; c < 10; c++) mx = fmaxf(mx, acc[c]);
        mx = fmaxf(mx, __shfl_xor_sync(0xffffffffu, mx, 1));
        mx = fmaxf(mx, __shfl_xor_sync(0xffffffffu, mx, 2));
        float se = 0.f;
#pragma unroll
        for (int c = 0; c < 10; c++) se += expf(acc[c] - mx);
        se += __shfl_xor_sync(0xffffffffu, se, 1);
        se += __shfl_xor_sync(0xffffffffu, se, 2);
        float lse = logf(se);
        if (k8 == 0) {
            float* o = out + (size_t)node * NCLS + c4 * 10;
#pragma unroll
            for (int c = 0; c < 10; c++) o[c] = acc[c] - mx - lse;
        }
    }
}

// ---------------------------------------------------------------------------
// kernel_launch
// ---------------------------------------------------------------------------
extern "C" void kernel_launch(void* const* d_in, const int* in_sizes, int n_in,
                              void* d_out, int out_size) {
    const float* x    = (const float*)d_in[0];
    const int*   ei   = (const int*)d_in[1];
    const float* Wr1  = (const float*)d_in[2];
    const float* b1   = (const float*)d_in[3];
    const float* Wt1  = (const float*)d_in[4];
    const float* Wr2  = (const float*)d_in[5];
    const float* b2   = (const float*)d_in[6];
    const float* Wt2  = (const float*)d_in[7];
    const float* Wl   = (const float*)d_in[8];
    const float* bl   = (const float*)d_in[9];
    float*       out  = (float*)d_out;

    const int N = in_sizes[0] / FDIM;
    const int E = in_sizes[1] / 2;
    const int* src = ei;
    const int* dst = ei + E;

    float *agg, *x1, *x2;
    int *deg, *rowptr, *cursor, *csr, *bsum, *boff;
    cudaGetSymbolAddress((void**)&agg,    g_agg);
    cudaGetSymbolAddress((void**)&x1,     g_x1);
    cudaGetSymbolAddress((void**)&x2,     g_x2);
    cudaGetSymbolAddress((void**)&deg,    g_deg);
    cudaGetSymbolAddress((void**)&rowptr, g_rowptr);
    cudaGetSymbolAddress((void**)&cursor, g_cursor);
    cudaGetSymbolAddress((void**)&csr,    g_csr);
    cudaGetSymbolAddress((void**)&bsum,   g_bsum);
    cudaGetSymbolAddress((void**)&boff,   g_boff);

    const int NB      = (N + SCAN_BLK - 1) / SCAN_BLK;      // <= 1024
    const int edgeBlk = (E + 255) / 256;
    const int nodeBlk = (N + 255) / 256;
    const int aggBlk  = (N + 7) / 8;
    const int gemmBlk = (N + 127) / 128;

    // ---- CSR build (once, reused by both layers) ----
    zero_int_kernel<<<nodeBlk, 256>>>(deg, N);
    hist_kernel<<<edgeBlk, 256>>>(dst, deg, E);
    bsum_kernel<<<NB, SCAN_BLK>>>(deg, bsum, N);
    scan_bsum_kernel<<<1, 1024>>>(bsum, boff, NB);
    scan_final_kernel<<<NB, SCAN_BLK>>>(deg, boff, rowptr, cursor, N);
    fill_kernel<<<edgeBlk, 256>>>(src, dst, cursor, csr, E);

    // ---- Layer 1 ----
    aggregate_kernel<<<aggBlk, 256>>>(x, rowptr, deg, csr, agg, N);
    gemm_tc<<<gemmBlk, 256>>>(agg, Wr1, x, Wt1, b1, x1, N);

    // ---- Layer 2 ----
    aggregate_kernel<<<aggBlk, 256>>>(x1, rowptr, deg, csr, agg, N);
    gemm_tc<<<gemmBlk, 256>>>(agg, Wr2, x1, Wt2, b2, x2, N);

    // ---- Head ----
    head_kernel<<<1024, 256>>>(x1, x2, Wl, bl, out, N);
}

// round 10
// speedup vs baseline: 3.8598x; 1.5333x over previous
#include <cuda_runtime.h>
#include <cstdint>
#include <cstddef>

#define FDIM 128
#define NMAX 100000
#define EMAX 1700000
#define NCLS 40
#define SCAN_BLK 256

static __device__ float g_agg[(size_t)NMAX * FDIM];
static __device__ float g_x1[(size_t)NMAX * FDIM];
static __device__ float g_x2[(size_t)NMAX * FDIM];
static __device__ int   g_deg[NMAX];
static __device__ int   g_rowptr[NMAX];
static __device__ int   g_cursor[NMAX];
static __device__ int   g_csr[EMAX];
static __device__ int   g_bsum[1024];
static __device__ int   g_boff[1024];

// ---------------------------------------------------------------------------
// CSR build
// ---------------------------------------------------------------------------
__global__ void zero_int_kernel(int* __restrict__ p, int n) {
    int i = blockIdx.x * blockDim.x + threadIdx.x;
    if (i < n) p[i] = 0;
}

__global__ void hist_kernel(const int* __restrict__ dst, int* __restrict__ deg, int E) {
    int e = blockIdx.x * blockDim.x + threadIdx.x;
    if (e < E) atomicAdd(deg + __ldg(dst + e), 1);
}

__global__ void bsum_kernel(const int* __restrict__ deg, int* __restrict__ bsum, int N) {
    __shared__ int s[SCAN_BLK];
    int i = blockIdx.x * SCAN_BLK + threadIdx.x;
    int v = (i < N) ? deg[i] : 0;
    s[threadIdx.x] = v;
    __syncthreads();
    for (int off = SCAN_BLK / 2; off > 0; off >>= 1) {
        if (threadIdx.x < off) s[threadIdx.x] += s[threadIdx.x + off];
        __syncthreads();
    }
    if (threadIdx.x == 0) bsum[blockIdx.x] = s[0];
}

__global__ void scan_bsum_kernel(const int* __restrict__ bsum, int* __restrict__ boff, int NB) {
    __shared__ int s[1024];
    int t = threadIdx.x;
    int v = (t < NB) ? bsum[t] : 0;
    s[t] = v;
    __syncthreads();
    for (int off = 1; off < 1024; off <<= 1) {
        int x = (t >= off) ? s[t - off] : 0;
        __syncthreads();
        s[t] += x;
        __syncthreads();
    }
    boff[t] = s[t] - v;
}

__global__ void scan_final_kernel(const int* __restrict__ deg, const int* __restrict__ boff,
                                  int* __restrict__ rowptr, int* __restrict__ cursor, int N) {
    __shared__ int s[SCAN_BLK];
    int i = blockIdx.x * SCAN_BLK + threadIdx.x;
    int t = threadIdx.x;
    int v = (i < N) ? deg[i] : 0;
    s[t] = v;
    __syncthreads();
    for (int off = 1; off < SCAN_BLK; off <<= 1) {
        int x = (t >= off) ? s[t - off] : 0;
        __syncthreads();
        s[t] += x;
        __syncthreads();
    }
    if (i < N) {
        int r = boff[blockIdx.x] + s[t] - v;
        rowptr[i] = r;
        cursor[i] = r;
    }
}

__global__ void fill_kernel(const int* __restrict__ src, const int* __restrict__ dst,
                            int* __restrict__ cursor, int* __restrict__ csr, int E) {
    int e = blockIdx.x * blockDim.x + threadIdx.x;
    if (e < E) {
        int pos = atomicAdd(cursor + __ldg(dst + e), 1);
        csr[pos] = __ldg(src + e);
    }
}

// ---------------------------------------------------------------------------
// Gather-aggregate: agg[i] = sum_{j in N(i)} x[j].  One warp/node, unroll 4.
// ---------------------------------------------------------------------------
__global__ __launch_bounds__(256)
void aggregate_kernel(const float* __restrict__ x,
                      const int* __restrict__ rowptr,
                      const int* __restrict__ deg,
                      const int* __restrict__ csr,
                      float* __restrict__ agg, int N) {
    int node = blockIdx.x * 8 + (threadIdx.x >> 5);
    if (node >= N) return;
    int lane = threadIdx.x & 31;
    int start = __ldg(rowptr + node);
    int end   = start + __ldg(deg + node);

    float4 acc = make_float4(0.f, 0.f, 0.f, 0.f);
    int p = start;
    for (; p + 4 <= end; p += 4) {
        int j0 = __ldg(csr + p);
        int j1 = __ldg(csr + p + 1);
        int j2 = __ldg(csr + p + 2);
        int j3 = __ldg(csr + p + 3);
        float4 v0 = *(const float4*)(x + (size_t)j0 * FDIM + lane * 4);
        float4 v1 = *(const float4*)(x + (size_t)j1 * FDIM + lane * 4);
        float4 v2 = *(const float4*)(x + (size_t)j2 * FDIM + lane * 4);
        float4 v3 = *(const float4*)(x + (size_t)j3 * FDIM + lane * 4);
        acc.x += v0.x + v1.x + v2.x + v3.x;
        acc.y += v0.y + v1.y + v2.y + v3.y;
        acc.z += v0.z + v1.z + v2.z + v3.z;
        acc.w += v0.w + v1.w + v2.w + v3.w;
    }
    for (; p < end; ++p) {
        int j = __ldg(csr + p);
        float4 v = *(const float4*)(x + (size_t)j * FDIM + lane * 4);
        acc.x += v.x; acc.y += v.y; acc.z += v.z; acc.w += v.w;
    }
    *(float4*)(agg + (size_t)node * FDIM + lane * 4) = acc;
}

// ---------------------------------------------------------------------------
// Tensor-core TF32 fused GraphConv GEMM.
// Strides 136 (== 8 mod 32): conflict-free fragment LDS; B stored via STS.128.
// ---------------------------------------------------------------------------
#define AS_STRIDE 136
#define BS_STRIDE 136

__device__ __forceinline__ uint32_t f2tf32(float f) {
    uint32_t r;
    asm("cvt.rna.tf32.f32 %0, %1;" : "=r"(r) : "f"(f));
    return r;
}

__global__ __launch_bounds__(256, 2)
void gemm_tc(const float* __restrict__ A1, const float* __restrict__ B1,
             const float* __restrict__ A2, const float* __restrict__ B2,
             const float* __restrict__ bias, float* __restrict__ C, int M) {
    __shared__ __align__(16) uint32_t As[2][16 * AS_STRIDE];   // [k][m]
    __shared__ __align__(16) uint32_t Bs[2][16 * BS_STRIDE];   // [k][n]

    const int tid  = threadIdx.x;
    const int lane = tid & 31;
    const int g    = lane >> 2;
    const int t    = lane & 3;
    const int warp = tid >> 5;
    const int wm   = (warp >> 2) * 64;
    const int wn   = (warp & 3) * 32;
    const int m0   = blockIdx.x * 128;

    float acc[4][4][4];
#pragma unroll
    for (int mi = 0; mi < 4; mi++)
#pragma unroll
        for (int ni = 0; ni < 4; ni++)
#pragma unroll
            for (int j = 0; j < 4; j++) acc[mi][ni][j] = 0.f;

    float4 ra[2], rb[2];

#define LDG_CHUNK(T) do {                                                       \
    const float* Ap = ((T) < 8) ? A1 : A2;                                      \
    const float* Bp = ((T) < 8) ? B1 : B2;                                      \
    const int kt = ((T) & 7) * 16;                                              \
    _Pragma("unroll")                                                           \
    for (int i = 0; i < 2; i++) {                                               \
        int idx  = tid + i * 256;                                               \
        int row  = idx >> 2;                                                    \
        int colq = idx & 3;                                                     \
        ra[i] = make_float4(0.f, 0.f, 0.f, 0.f);                                \
        if (m0 + row < M)                                                       \
            ra[i] = *(const float4*)(Ap + (size_t)(m0 + row) * FDIM + kt + colq * 4); \
        int k   = idx >> 5;                                                     \
        int n4  = idx & 31;                                                     \
        rb[i] = *(const float4*)(Bp + (size_t)(kt + k) * FDIM + n4 * 4);        \
    }                                                                           \
} while (0)

#define STS_CHUNK(BUF) do {                                                     \
    _Pragma("unroll")                                                           \
    for (int i = 0; i < 2; i++) {                                               \
        int idx  = tid + i * 256;                                               \
        int row  = idx >> 2;                                                    \
        int colq = idx & 3;                                                     \
        As[BUF][(colq * 4 + 0) * AS_STRIDE + row] = f2tf32(ra[i].x);            \
        As[BUF][(colq * 4 + 1) * AS_STRIDE + row] = f2tf32(ra[i].y);            \
        As[BUF][(colq * 4 + 2) * AS_STRIDE + row] = f2tf32(ra[i].z);            \
        As[BUF][(colq * 4 + 3) * AS_STRIDE + row] = f2tf32(ra[i].w);            \
        int k  = idx >> 5;                                                      \
        int n4 = idx & 31;                                                      \
        uint4 u;                                                                \
        u.x = f2tf32(rb[i].x); u.y = f2tf32(rb[i].y);                           \
        u.z = f2tf32(rb[i].z); u.w = f2tf32(rb[i].w);                           \
        *(uint4*)&Bs[BUF][k * BS_STRIDE + n4 * 4] = u;                          \
    }                                                                           \
} while (0)

#define COMPUTE(BUF) do {                                                       \
    _Pragma("unroll")                                                           \
    for (int ks = 0; ks < 2; ks++) {                                            \
        uint32_t af[4][4];                                                      \
        uint32_t bf[4][2];                                                      \
        _Pragma("unroll")                                                       \
        for (int mi = 0; mi < 4; mi++) {                                        \
            int mb = wm + mi * 16;                                              \
            af[mi][0] = As[BUF][(ks * 8 + t    ) * AS_STRIDE + mb + g    ];     \
            af[mi][1] = As[BUF][(ks * 8 + t    ) * AS_STRIDE + mb + g + 8];     \
            af[mi][2] = As[BUF][(ks * 8 + t + 4) * AS_STRIDE + mb + g    ];     \
            af[mi][3] = As[BUF][(ks * 8 + t + 4) * AS_STRIDE + mb + g + 8];     \
        }                                                                       \
        _Pragma("unroll")                                                       \
        for (int ni = 0; ni < 4; ni++) {                                        \
            int nb = wn + ni * 8;                                               \
            bf[ni][0] = Bs[BUF][(ks * 8 + t    ) * BS_STRIDE + nb + g];         \
            bf[ni][1] = Bs[BUF][(ks * 8 + t + 4) * BS_STRIDE + nb + g];         \
        }                                                                       \
        _Pragma("unroll")                                                       \
        for (int mi = 0; mi < 4; mi++)                                          \
        _Pragma("unroll")                                                       \
        for (int ni = 0; ni < 4; ni++) {                                        \
            asm volatile(                                                       \
                "mma.sync.aligned.m16n8k8.row.col.f32.tf32.tf32.f32 "           \
                "{%0,%1,%2,%3}, {%4,%5,%6,%7}, {%8,%9}, {%0,%1,%2,%3};"         \
                : "+f"(acc[mi][ni][0]), "+f"(acc[mi][ni][1]),                   \
                  "+f"(acc[mi][ni][2]), "+f"(acc[mi][ni][3])                    \
                : "r"(af[mi][0]), "r"(af[mi][1]), "r"(af[mi][2]), "r"(af[mi][3]), \
                  "r"(bf[ni][0]), "r"(bf[ni][1]));                              \
        }                                                                       \
    }                                                                           \
} while (0)

    LDG_CHUNK(0);
    STS_CHUNK(0);
    __syncthreads();

    for (int tch = 0; tch < 16; tch++) {
        const int buf = tch & 1;
        if (tch < 15) LDG_CHUNK(tch + 1);
        COMPUTE(buf);
        if (tch < 15) {
            STS_CHUNK(buf ^ 1);
            __syncthreads();
        }
    }
#undef LDG_CHUNK
#undef STS_CHUNK
#undef COMPUTE

    float2 bb[4];
#pragma unroll
    for (int ni = 0; ni < 4; ni++) {
        int col = wn + ni * 8 + t * 2;
        bb[ni].x = __ldg(bias + col);
        bb[ni].y = __ldg(bias + col + 1);
    }
#pragma unroll
    for (int mi = 0; mi < 4; mi++) {
        int row0 = m0 + wm + mi * 16 + g;
        int row1 = row0 + 8;
#pragma unroll
        for (int ni = 0; ni < 4; ni++) {
            int col = wn + ni * 8 + t * 2;
            if (row0 < M) {
                float2 v;
                v.x = fmaxf(acc[mi][ni][0] + bb[ni].x, 0.f);
                v.y = fmaxf(acc[mi][ni][1] + bb[ni].y, 0.f);
                *(float2*)(C + (size_t)row0 * FDIM + col) = v;
            }
            if (row1 < M) {
                float2 v;
                v.x = fmaxf(acc[mi][ni][2] + bb[ni].x, 0.f);
                v.y = fmaxf(acc[mi][ni][3] + bb[ni].y, 0.f);
                *(float2*)(C + (size_t)row1 * FDIM + col) = v;
            }
        }
    }
}

// ---------------------------------------------------------------------------
// Head as TF32 mma GEMM with fused log_softmax epilogue.
//   logits = [x1|x2] @ Wl + bl  (K=256, N=40), out = log_softmax(logits)
// CTA: 128 rows, 8 warps x 16 rows. W resident in smem for the whole CTA.
// A chunked BK=32, m-major stride 36 (conflict-free fragment LDS).
// ---------------------------------------------------------------------------
#define HBK 32
#define HAS_STRIDE 36
#define HEAD_SMEM_BYTES ((256 * NCLS + 128 * HAS_STRIDE + NCLS) * 4)

__global__ __launch_bounds__(256)
void head_gemm(const float* __restrict__ x1, const float* __restrict__ x2,
               const float* __restrict__ Wl, const float* __restrict__ bl,
               float* __restrict__ out, int N) {
    extern __shared__ uint32_t sh[];
    uint32_t* Bs  = sh;                      // [256][40] tf32
    uint32_t* As2 = sh + 256 * NCLS;         // [128][36] tf32 (m-major)
    float*    bs  = (float*)(As2 + 128 * HAS_STRIDE);  // [40]

    const int tid  = threadIdx.x;
    const int lane = tid & 31;
    const int g    = lane >> 2;
    const int t    = lane & 3;
    const int warp = tid >> 5;
    const int wrow = warp * 16;
    const int m0   = blockIdx.x * 128;

    // Load W (256x40) and bias into smem once.
    for (int i = tid; i < 256 * NCLS; i += 256) Bs[i] = f2tf32(__ldg(Wl + i));
    if (tid < NCLS) bs[tid] = __ldg(bl + tid);

    float acc[5][4];
#pragma unroll
    for (int ni = 0; ni < 5; ni++)
#pragma unroll
        for (int j = 0; j < 4; j++) acc[ni][j] = 0.f;

    for (int kc = 0; kc < 8; kc++) {
        const float* src = (kc < 4) ? x1 : x2;
        const int kb = (kc & 3) * HBK;
        __syncthreads();
        // Load A chunk: 128 rows x 32 k -> As2 (m-major), coalesced LDG.
#pragma unroll
        for (int i = 0; i < 4; i++) {
            int idx = tid + i * 256;      // 0..1023
            int row = idx >> 3;           // 0..127
            int q   = idx & 7;            // 0..7 (float4 within 32 k)
            float4 v = make_float4(0.f, 0.f, 0.f, 0.f);
            if (m0 + row < N)
                v = *(const float4*)(src + (size_t)(m0 + row) * FDIM + kb + q * 4);
            uint32_t* ap = &As2[row * HAS_STRIDE + q * 4];
            ap[0] = f2tf32(v.x); ap[1] = f2tf32(v.y);
            ap[2] = f2tf32(v.z); ap[3] = f2tf32(v.w);
        }
        __syncthreads();

#pragma unroll
        for (int ks = 0; ks < 4; ks++) {
            uint32_t af[4];
            af[0] = As2[(wrow + g    ) * HAS_STRIDE + ks * 8 + t    ];
            af[1] = As2[(wrow + g + 8) * HAS_STRIDE + ks * 8 + t    ];
            af[2] = As2[(wrow + g    ) * HAS_STRIDE + ks * 8 + t + 4];
            af[3] = As2[(wrow + g + 8) * HAS_STRIDE + ks * 8 + t + 4];
            const int kg = kc * HBK + ks * 8;
#pragma unroll
            for (int ni = 0; ni < 5; ni++) {
                uint32_t b0 = Bs[(kg + t    ) * NCLS + ni * 8 + g];
                uint32_t b1 = Bs[(kg + t + 4) * NCLS + ni * 8 + g];
                asm volatile(
                    "mma.sync.aligned.m16n8k8.row.col.f32.tf32.tf32.f32 "
                    "{%0,%1,%2,%3}, {%4,%5,%6,%7}, {%8,%9}, {%0,%1,%2,%3};"
                    : "+f"(acc[ni][0]), "+f"(acc[ni][1]),
                      "+f"(acc[ni][2]), "+f"(acc[ni][3])
                    : "r"(af[0]), "r"(af[1]), "r"(af[2]), "r"(af[3]),
                      "r"(b0), "r"(b1));
            }
        }
    }

    // Epilogue: per-row bias + log_softmax.
    // Lane (g,t) holds rows {rowA=wrow+g, rowB=wrow+g+8}, cols ni*8+2t(+1).
    float la[10], lb[10];
#pragma unroll
    for (int ni = 0; ni < 5; ni++) {
        float b0 = bs[ni * 8 + t * 2];
        float b1 = bs[ni * 8 + t * 2 + 1];
        la[ni * 2]     = acc[ni][0] + b0;
        la[ni * 2 + 1] = acc[ni][1] + b1;
        lb[ni * 2]     = acc[ni][2] + b0;
        lb[ni * 2 + 1] = acc[ni][3] + b1;
    }
    float mA = la[0], mB = lb[0];
#pragma unroll
    for (int c = 1; c < 10; c++) { mA = fmaxf(mA, la[c]); mB = fmaxf(mB, lb[c]); }
    mA = fmaxf(mA, __shfl_xor_sync(0xffffffffu, mA, 1));
    mA = fmaxf(mA, __shfl_xor_sync(0xffffffffu, mA, 2));
    mB = fmaxf(mB, __shfl_xor_sync(0xffffffffu, mB, 1));
    mB = fmaxf(mB, __shfl_xor_sync(0xffffffffu, mB, 2));
    float sA = 0.f, sB = 0.f;
#pragma unroll
    for (int c = 0; c < 10; c++) { sA += expf(la[c] - mA); sB += expf(lb[c] - mB); }
    sA += __shfl_xor_sync(0xffffffffu, sA, 1);
    sA += __shfl_xor_sync(0xffffffffu, sA, 2);
    sB += __shfl_xor_sync(0xffffffffu, sB, 1);
    sB += __shfl_xor_sync(0xffffffffu, sB, 2);
    float oA = mA + logf(sA);
    float oB = mB + logf(sB);

    int rowA = m0 + wrow + g;
    int rowB = rowA + 8;
#pragma unroll
    for (int ni = 0; ni < 5; ni++) {
        int col = ni * 8 + t * 2;
        if (rowA < N) {
            float2 v; v.x = la[ni * 2] - oA; v.y = la[ni * 2 + 1] - oA;
            *(float2*)(out + (size_t)rowA * NCLS + col) = v;
        }
        if (rowB < N) {
            float2 v; v.x = lb[ni * 2] - oB; v.y = lb[ni * 2 + 1] - oB;
            *(float2*)(out + (size_t)rowB * NCLS + col) = v;
        }
    }
}

// ---------------------------------------------------------------------------
// kernel_launch
// ---------------------------------------------------------------------------
extern "C" void kernel_launch(void* const* d_in, const int* in_sizes, int n_in,
                              void* d_out, int out_size) {
    const float* x    = (const float*)d_in[0];
    const int*   ei   = (const int*)d_in[1];
    const float* Wr1  = (const float*)d_in[2];
    const float* b1   = (const float*)d_in[3];
    const float* Wt1  = (const float*)d_in[4];
    const float* Wr2  = (const float*)d_in[5];
    const float* b2   = (const float*)d_in[6];
    const float* Wt2  = (const float*)d_in[7];
    const float* Wl   = (const float*)d_in[8];
    const float* bl   = (const float*)d_in[9];
    float*       out  = (float*)d_out;

    const int N = in_sizes[0] / FDIM;
    const int E = in_sizes[1] / 2;
    const int* src = ei;
    const int* dst = ei + E;

    float *agg, *x1, *x2;
    int *deg, *rowptr, *cursor, *csr, *bsum, *boff;
    cudaGetSymbolAddress((void**)&agg,    g_agg);
    cudaGetSymbolAddress((void**)&x1,     g_x1);
    cudaGetSymbolAddress((void**)&x2,     g_x2);
    cudaGetSymbolAddress((void**)&deg,    g_deg);
    cudaGetSymbolAddress((void**)&rowptr, g_rowptr);
    cudaGetSymbolAddress((void**)&cursor, g_cursor);
    cudaGetSymbolAddress((void**)&csr,    g_csr);
    cudaGetSymbolAddress((void**)&bsum,   g_bsum);
    cudaGetSymbolAddress((void**)&boff,   g_boff);

    static int head_attr_done = 0;
    if (!head_attr_done) {
        cudaFuncSetAttribute(head_gemm, cudaFuncAttributeMaxDynamicSharedMemorySize,
                             HEAD_SMEM_BYTES);
        head_attr_done = 1;
    }

    const int NB      = (N + SCAN_BLK - 1) / SCAN_BLK;
    const int edgeBlk = (E + 255) / 256;
    const int nodeBlk = (N + 255) / 256;
    const int aggBlk  = (N + 7) / 8;
    const int gemmBlk = (N + 127) / 128;

    // ---- CSR build (once, reused by both layers) ----
    zero_int_kernel<<<nodeBlk, 256>>>(deg, N);
    hist_kernel<<<edgeBlk, 256>>>(dst, deg, E);
    bsum_kernel<<<NB, SCAN_BLK>>>(deg, bsum, N);
    scan_bsum_kernel<<<1, 1024>>>(bsum, boff, NB);
    scan_final_kernel<<<NB, SCAN_BLK>>>(deg, boff, rowptr, cursor, N);
    fill_kernel<<<edgeBlk, 256>>>(src, dst, cursor, csr, E);

    // ---- Layer 1 ----
    aggregate_kernel<<<aggBlk, 256>>>(x, rowptr, deg, csr, agg, N);
    gemm_tc<<<gemmBlk, 256>>>(agg, Wr1, x, Wt1, b1, x1, N);

    // ---- Layer 2 ----
    aggregate_kernel<<<aggBlk, 256>>>(x1, rowptr, deg, csr, agg, N);
    gemm_tc<<<gemmBlk, 256>>>(agg, Wr2, x1, Wt2, b2, x2, N);

    // ---- Head (fused GEMM + log_softmax) ----
    head_gemm<<<gemmBlk, 256, HEAD_SMEM_BYTES>>>(x1, x2, Wl, bl, out, N);
}